// round 4
// baseline (speedup 1.0000x reference)
#include <cuda_runtime.h>
#include <cuda_fp16.h>
#include <math.h>

#define NMAX 50048
#define EMAX 800032
#define SLOPE 0.2f

// ---- scratch (no allocs allowed) ----
__device__ float  g_h[(size_t)NMAX * 128];   // transformed features (fp32)
__device__ __half g_hh[(size_t)NMAX * 128];  // transformed features (fp16 copy)
__device__ float  g_as[NMAX];                // src logits
__device__ float  g_ad[NMAX];                // dst logits
__device__ int    g_deg[NMAX];               // in-degree histogram
__device__ int    g_scan[NMAX];              // block-local exclusive scan
__device__ int    g_bt[256];                 // per-block totals
__device__ int    g_off[NMAX + 1];           // CSR offsets
__device__ int    g_cur[NMAX];               // fill cursors
__device__ int    g_eidx[EMAX];              // CSR: src index per slot
__device__ int    g_is64;

// ============================================================
// K0: detect whether edge_index buffer is int64 or int32
// ============================================================
__global__ void detect_kernel(const long long* __restrict__ ei, int E, int N) {
    __shared__ int bad;
    if (threadIdx.x == 0) bad = 0;
    __syncthreads();
    int i = threadIdx.x;
    if (i < E) {
        long long v = ei[i];
        if (v < 0 || v >= (long long)N) atomicOr(&bad, 1);
    }
    __syncthreads();
    if (threadIdx.x == 0) g_is64 = bad ? 0 : 1;
}

// ============================================================
// K1: h = x @ W  (fp32 FFMA, 128x128 tile, 8x8 microtile)
// epilogue: fp32 + fp16 copies, and zero g_deg slice
// ============================================================
__global__ __launch_bounds__(256, 2)
void gemm128(const float* __restrict__ x, const float* __restrict__ W, int N) {
    __shared__ float xs[32][132];  // xs[k][row]
    __shared__ float ws[32][132];  // ws[k][col]

    int tid = threadIdx.x;
    int tx = tid & 15;
    int ty = tid >> 4;
    int rowBase = blockIdx.x * 128;

    // zero degree histogram slice (for the fused logits|hist kernel)
    {
        int di = rowBase + tid;
        if (tid < 128 && di < N) g_deg[di] = 0;
    }

    float acc[8][8];
#pragma unroll
    for (int i = 0; i < 8; i++)
#pragma unroll
        for (int j = 0; j < 8; j++) acc[i][j] = 0.f;

    for (int kc = 0; kc < 128; kc += 32) {
#pragma unroll
        for (int it = 0; it < 4; it++) {
            int v = tid + it * 256;
            int r = v >> 3;
            int kq = v & 7;
            int gr = rowBase + r;
            float4 xv = make_float4(0.f, 0.f, 0.f, 0.f);
            if (gr < N) xv = *(const float4*)&x[(size_t)gr * 128 + kc + kq * 4];
            xs[kq * 4 + 0][r] = xv.x;
            xs[kq * 4 + 1][r] = xv.y;
            xs[kq * 4 + 2][r] = xv.z;
            xs[kq * 4 + 3][r] = xv.w;
        }
#pragma unroll
        for (int it = 0; it < 4; it++) {
            int v = tid + it * 256;
            int k = v >> 5;
            int nq = v & 31;
            float4 wv = *(const float4*)&W[(size_t)(kc + k) * 128 + nq * 4];
            *(float4*)&ws[k][nq * 4] = wv;
        }
        __syncthreads();

#pragma unroll
        for (int k = 0; k < 32; k++) {
            float a[8], b[8];
            *(float4*)&a[0] = *(const float4*)&xs[k][ty * 8];
            *(float4*)&a[4] = *(const float4*)&xs[k][ty * 8 + 4];
            *(float4*)&b[0] = *(const float4*)&ws[k][tx * 8];
            *(float4*)&b[4] = *(const float4*)&ws[k][tx * 8 + 4];
#pragma unroll
            for (int i = 0; i < 8; i++)
#pragma unroll
                for (int j = 0; j < 8; j++)
                    acc[i][j] += a[i] * b[j];
        }
        __syncthreads();
    }

#pragma unroll
    for (int i = 0; i < 8; i++) {
        int gr = rowBase + ty * 8 + i;
        if (gr < N) {
            *(float4*)&g_h[(size_t)gr * 128 + tx * 8] =
                make_float4(acc[i][0], acc[i][1], acc[i][2], acc[i][3]);
            *(float4*)&g_h[(size_t)gr * 128 + tx * 8 + 4] =
                make_float4(acc[i][4], acc[i][5], acc[i][6], acc[i][7]);
            __half2 h0 = __floats2half2_rn(acc[i][0], acc[i][1]);
            __half2 h1 = __floats2half2_rn(acc[i][2], acc[i][3]);
            __half2 h2 = __floats2half2_rn(acc[i][4], acc[i][5]);
            __half2 h3 = __floats2half2_rn(acc[i][6], acc[i][7]);
            __half2* hp = (__half2*)&g_hh[(size_t)gr * 128 + tx * 8];
            hp[0] = h0; hp[1] = h1; hp[2] = h2; hp[3] = h3;
        }
    }
}

// ============================================================
// K2: fused [node logits | dst histogram]
// blocks [0, nbLogits): warp-per-node logits
// blocks [nbLogits, ...): 8-edges-per-thread histogram (vectorized)
// ============================================================
__global__ __launch_bounds__(256)
void logits_hist(const float* __restrict__ att_s, const float* __restrict__ att_d,
                 int N, const long long* __restrict__ ei, int E, int nbLogits) {
    if ((int)blockIdx.x < nbLogits) {
        int warp = (blockIdx.x * 256 + threadIdx.x) >> 5;
        int lane = threadIdx.x & 31;
        if (warp >= N) return;
        float4 hv = *(const float4*)&g_h[(size_t)warp * 128 + lane * 4];
        float4 s4 = *(const float4*)&att_s[lane * 4];
        float4 d4 = *(const float4*)&att_d[lane * 4];
        float s = hv.x * s4.x + hv.y * s4.y + hv.z * s4.z + hv.w * s4.w;
        float d = hv.x * d4.x + hv.y * d4.y + hv.z * d4.z + hv.w * d4.w;
#pragma unroll
        for (int o = 16; o > 0; o >>= 1) {
            s += __shfl_xor_sync(0xffffffffu, s, o);
            d += __shfl_xor_sync(0xffffffffu, d, o);
        }
        if (lane == 0) {
            g_as[warp] = s;
            g_ad[warp] = d;
        }
    } else {
        int t = (blockIdx.x - nbLogits) * 256 + threadIdx.x;
        int base = t * 8;
        if (base >= E) return;
        int n = E - base; if (n > 8) n = 8;
        int d[8];
        if (g_is64) {
            if (n == 8 && (E & 1) == 0) {
                const longlong2* p = (const longlong2*)(ei + (size_t)E + base);
#pragma unroll
                for (int j = 0; j < 4; j++) {
                    longlong2 v = p[j];
                    d[2 * j] = (int)v.x; d[2 * j + 1] = (int)v.y;
                }
            } else {
                for (int j = 0; j < n; j++) d[j] = (int)ei[(size_t)E + base + j];
            }
        } else {
            const int* p32 = (const int*)ei;
            if (n == 8 && (E & 3) == 0) {
                const int4* p = (const int4*)(p32 + E + base);
                int4 v0 = p[0], v1 = p[1];
                d[0] = v0.x; d[1] = v0.y; d[2] = v0.z; d[3] = v0.w;
                d[4] = v1.x; d[5] = v1.y; d[6] = v1.z; d[7] = v1.w;
            } else {
                for (int j = 0; j < n; j++) d[j] = p32[E + base + j];
            }
        }
#pragma unroll
        for (int j = 0; j < 8; j++)
            if (j < n) atomicAdd(&g_deg[d[j]], 1);
    }
}

// ============================================================
// K3a: block-local exclusive scan (256 per block) + block totals
// ============================================================
__global__ void scan_blocks(int N) {
    __shared__ int sh[256];
    int i = blockIdx.x * 256 + threadIdx.x;
    int v = (i < N) ? g_deg[i] : 0;
    sh[threadIdx.x] = v;
    __syncthreads();
#pragma unroll
    for (int o = 1; o < 256; o <<= 1) {
        int t = (threadIdx.x >= o) ? sh[threadIdx.x - o] : 0;
        __syncthreads();
        sh[threadIdx.x] += t;
        __syncthreads();
    }
    if (i < N) g_scan[i] = sh[threadIdx.x] - v;  // exclusive
    if (threadIdx.x == 255) g_bt[blockIdx.x] = sh[255];
}

// ============================================================
// K3b: scan block totals (single block), set g_off[N]=E
// ============================================================
__global__ void scan_totals(int nb, int E, int N) {
    __shared__ int sh[256];
    int v = (threadIdx.x < nb) ? g_bt[threadIdx.x] : 0;
    sh[threadIdx.x] = v;
    __syncthreads();
#pragma unroll
    for (int o = 1; o < 256; o <<= 1) {
        int t = (threadIdx.x >= o) ? sh[threadIdx.x - o] : 0;
        __syncthreads();
        sh[threadIdx.x] += t;
        __syncthreads();
    }
    g_bt[threadIdx.x] = sh[threadIdx.x] - v;
    if (threadIdx.x == 0) g_off[N] = E;
}

// ============================================================
// K3c: add back -> CSR offsets + cursors
// ============================================================
__global__ void scan_addback(int N) {
    int i = blockIdx.x * 256 + threadIdx.x;
    if (i >= N) return;
    int o = g_scan[i] + g_bt[blockIdx.x];
    g_off[i] = o;
    g_cur[i] = o;
}

// ============================================================
// K4: fill CSR slots with src indices (8 edges/thread, vectorized)
// ============================================================
__global__ __launch_bounds__(256)
void fill_kernel(const long long* __restrict__ ei, int E) {
    int t = blockIdx.x * 256 + threadIdx.x;
    int base = t * 8;
    if (base >= E) return;
    int n = E - base; if (n > 8) n = 8;
    int s[8], d[8];
    if (g_is64) {
        if (n == 8 && (E & 1) == 0) {
            const longlong2* ps = (const longlong2*)(ei + base);
            const longlong2* pd = (const longlong2*)(ei + (size_t)E + base);
#pragma unroll
            for (int j = 0; j < 4; j++) {
                longlong2 vs = ps[j], vd = pd[j];
                s[2 * j] = (int)vs.x; s[2 * j + 1] = (int)vs.y;
                d[2 * j] = (int)vd.x; d[2 * j + 1] = (int)vd.y;
            }
        } else {
            for (int j = 0; j < n; j++) {
                s[j] = (int)ei[base + j];
                d[j] = (int)ei[(size_t)E + base + j];
            }
        }
    } else {
        const int* p32 = (const int*)ei;
        if (n == 8 && (E & 3) == 0) {
            const int4* ps = (const int4*)(p32 + base);
            const int4* pd = (const int4*)(p32 + E + base);
            int4 a0 = ps[0], a1 = ps[1], b0 = pd[0], b1 = pd[1];
            s[0] = a0.x; s[1] = a0.y; s[2] = a0.z; s[3] = a0.w;
            s[4] = a1.x; s[5] = a1.y; s[6] = a1.z; s[7] = a1.w;
            d[0] = b0.x; d[1] = b0.y; d[2] = b0.z; d[3] = b0.w;
            d[4] = b1.x; d[5] = b1.y; d[6] = b1.z; d[7] = b1.w;
        } else {
            for (int j = 0; j < n; j++) {
                s[j] = p32[base + j];
                d[j] = p32[E + base + j];
            }
        }
    }
#pragma unroll
    for (int j = 0; j < 8; j++)
        if (j < n) {
            int slot = atomicAdd(&g_cur[d[j]], 1);
            g_eidx[slot] = s[j];
        }
}

// ============================================================
// K5: fused softmax + aggregate (warp per dst, fp16 gathers)
// ============================================================
__global__ __launch_bounds__(256)
void aggregate(float* __restrict__ out, const float* __restrict__ bias, int N) {
    int node = (blockIdx.x * blockDim.x + threadIdx.x) >> 5;
    int lane = threadIdx.x & 31;
    if (node >= N) return;

    float ad = g_ad[node];
    float e0 = g_as[node] + ad;
    e0 = e0 > 0.f ? e0 : SLOPE * e0;
    float pself = expf(e0);

    const __half2* hp0 = (const __half2*)&g_hh[(size_t)node * 128 + lane * 4];
    float2 f0 = __half22float2(hp0[0]);
    float2 f1 = __half22float2(hp0[1]);
    float4 acc;
    acc.x = pself * f0.x;
    acc.y = pself * f0.y;
    acc.z = pself * f1.x;
    acc.w = pself * f1.y;
    float den = pself;

    int beg = g_off[node];
    int end = g_off[node + 1];
    for (int base = beg; base < end; base += 32) {
        int e = base + lane;
        int s = (e < end) ? g_eidx[e] : 0;
        int nv = end - base;
        if (nv > 32) nv = 32;
#pragma unroll 4
        for (int j = 0; j < nv; j++) {
            int sj = __shfl_sync(0xffffffffu, s, j);
            float v = g_as[sj] + ad;
            v = v > 0.f ? v : SLOPE * v;
            float p = expf(v);
            const __half2* hp = (const __half2*)&g_hh[(size_t)sj * 128 + lane * 4];
            float2 a0 = __half22float2(hp[0]);
            float2 a1 = __half22float2(hp[1]);
            den += p;
            acc.x += p * a0.x;
            acc.y += p * a0.y;
            acc.z += p * a1.x;
            acc.w += p * a1.y;
        }
    }

    float inv = 1.f / den;
    float4 b = *(const float4*)&bias[lane * 4];
    float4 o;
    o.x = acc.x * inv + b.x;
    o.y = acc.y * inv + b.y;
    o.z = acc.z * inv + b.z;
    o.w = acc.w * inv + b.w;
    *(float4*)&out[(size_t)node * 128 + lane * 4] = o;
}

// ============================================================
extern "C" void kernel_launch(void* const* d_in, const int* in_sizes, int n_in,
                              void* d_out, int out_size) {
    const float*     x     = (const float*)d_in[0];
    const long long* ei    = (const long long*)d_in[1];
    const float*     W     = (const float*)d_in[2];
    const float*     att_s = (const float*)d_in[3];
    const float*     att_d = (const float*)d_in[4];
    const float*     bias  = (const float*)d_in[5];
    float*           out   = (float*)d_out;

    int N = in_sizes[0] / 128;
    int E = in_sizes[1] / 2;
    int nb = (N + 255) / 256;
    int nbLogits = (N + 7) / 8;                       // 8 warps per block
    int nbHist = ((E + 7) / 8 + 255) / 256;           // 8 edges per thread

    detect_kernel<<<1, 1024>>>(ei, E, N);
    gemm128<<<(N + 127) / 128, 256>>>(x, W, N);
    logits_hist<<<nbLogits + nbHist, 256>>>(att_s, att_d, N, ei, E, nbLogits);
    scan_blocks<<<nb, 256>>>(N);
    scan_totals<<<1, 256>>>(nb, E, N);
    scan_addback<<<nb, 256>>>(N);
    fill_kernel<<<((E + 7) / 8 + 255) / 256, 256>>>(ei, E);
    aggregate<<<(N * 32 + 255) / 256, 256>>>(out, bias, N);
}

// round 5
// speedup vs baseline: 1.1607x; 1.1607x over previous
#include <cuda_runtime.h>
#include <cuda_fp16.h>
#include <math.h>

#define NMAX 50048
#define EMAX 800032
#define SLOPE 0.2f

// ---- scratch (no allocs allowed) ----
__device__ float  g_h[(size_t)NMAX * 128];   // transformed features (fp32)
__device__ __half g_hh[(size_t)NMAX * 128];  // transformed features (fp16 copy)
__device__ __half g_Wh[128 * 128];           // W hi, transposed [n][k]
__device__ __half g_Wl[128 * 128];           // W lo, transposed [n][k]
__device__ float  g_as[NMAX];                // src logits
__device__ float  g_ad[NMAX];                // dst logits
__device__ int    g_deg[NMAX];               // in-degree histogram
__device__ int    g_scan[NMAX];              // block-local exclusive scan
__device__ int    g_bt[256];                 // per-block totals
__device__ int    g_off[NMAX + 1];           // CSR offsets
__device__ int    g_cur[NMAX];               // fill cursors
__device__ int    g_eidx[EMAX];              // CSR: src index per slot
__device__ int    g_is64;

// ============================================================
// helpers
// ============================================================
__device__ __forceinline__ void mma_f16(float* c, const unsigned* a, const unsigned* b) {
    asm volatile(
        "mma.sync.aligned.m16n8k16.row.col.f32.f16.f16.f32 "
        "{%0,%1,%2,%3},{%4,%5,%6,%7},{%8,%9},{%0,%1,%2,%3};"
        : "+f"(c[0]), "+f"(c[1]), "+f"(c[2]), "+f"(c[3])
        : "r"(a[0]), "r"(a[1]), "r"(a[2]), "r"(a[3]), "r"(b[0]), "r"(b[1]));
}

// ============================================================
// K0: detect whether edge_index buffer is int64 or int32
// ============================================================
__global__ void detect_kernel(const long long* __restrict__ ei, int E, int N) {
    __shared__ int bad;
    if (threadIdx.x == 0) bad = 0;
    __syncthreads();
    int i = threadIdx.x;
    if (i < E) {
        long long v = ei[i];
        if (v < 0 || v >= (long long)N) atomicOr(&bad, 1);
    }
    __syncthreads();
    if (threadIdx.x == 0) g_is64 = bad ? 0 : 1;
}

// ============================================================
// K0b: pre-split W into fp16 hi/lo, transposed to [n][k]
// ============================================================
__global__ void wprep_kernel(const float* __restrict__ W) {
    int i = blockIdx.x * 256 + threadIdx.x;  // 16384 elements
    int k = i >> 7, n = i & 127;
    float w = W[i];                          // W[k][n] row-major
    __half h = __float2half_rn(w);
    __half l = __float2half_rn(w - __half2float(h));
    g_Wh[n * 128 + k] = h;
    g_Wl[n * 128 + k] = l;
}

// ============================================================
// K1: h = x @ W via fp16x3 split tensor-core MMA (fp32-equivalent)
// block tile 128x128, 8 warps (4m x 2n), warp tile 32x64
// ============================================================
__global__ __launch_bounds__(256)
void gemm_f16x3(const float* __restrict__ x, int N) {
    __shared__ __half xs_h[128][40];  // [row][k], pad 40
    __shared__ __half xs_l[128][40];
    __shared__ __half ws_h[128][40];  // [col][k]
    __shared__ __half ws_l[128][40];

    int tid = threadIdx.x;
    int warp = tid >> 5, lane = tid & 31;
    int warpM = warp >> 1;   // 0..3  -> 32-row slab
    int warpN = warp & 1;    // 0..1  -> 64-col slab
    int g = lane >> 2, tg = lane & 3;
    int rowBase = blockIdx.x * 128;

    // zero degree histogram slice (for the fused logits|hist kernel)
    if (tid < 128 && rowBase + tid < N) g_deg[rowBase + tid] = 0;

    float acc[2][8][4];
#pragma unroll
    for (int mt = 0; mt < 2; mt++)
#pragma unroll
        for (int nt = 0; nt < 8; nt++)
#pragma unroll
            for (int q = 0; q < 4; q++) acc[mt][nt][q] = 0.f;

    for (int kc = 0; kc < 128; kc += 32) {
        // stage x tile with fp16 hi/lo split: 128 rows x 32 k
#pragma unroll
        for (int it = 0; it < 4; it++) {
            int v = tid + it * 256;      // 0..1023 float4 slots
            int r = v >> 3;              // 0..127
            int kq = v & 7;              // 0..7
            int gr = rowBase + r;
            float4 xv = make_float4(0.f, 0.f, 0.f, 0.f);
            if (gr < N) xv = *(const float4*)&x[(size_t)gr * 128 + kc + kq * 4];
            __half2 h01 = __floats2half2_rn(xv.x, xv.y);
            __half2 h23 = __floats2half2_rn(xv.z, xv.w);
            float2 b01 = __half22float2(h01);
            float2 b23 = __half22float2(h23);
            __half2 l01 = __floats2half2_rn(xv.x - b01.x, xv.y - b01.y);
            __half2 l23 = __floats2half2_rn(xv.z - b23.x, xv.w - b23.y);
            *(__half2*)&xs_h[r][kq * 4]     = h01;
            *(__half2*)&xs_h[r][kq * 4 + 2] = h23;
            *(__half2*)&xs_l[r][kq * 4]     = l01;
            *(__half2*)&xs_l[r][kq * 4 + 2] = l23;
        }
        // stage pre-split W chunk: [n][kc..kc+31], 128 rows x 32 halves
#pragma unroll
        for (int it = 0; it < 2; it++) {
            int v = tid + it * 256;      // 0..511 int4 slots
            int n = v >> 2;              // 0..127
            int q = v & 3;               // 0..3 (int4 = 8 halves)
            *(int4*)&ws_h[n][q * 8] = *(const int4*)&g_Wh[n * 128 + kc + q * 8];
            *(int4*)&ws_l[n][q * 8] = *(const int4*)&g_Wl[n * 128 + kc + q * 8];
        }
        __syncthreads();

#pragma unroll
        for (int ks = 0; ks < 2; ks++) {
            int kb = ks * 16;
            unsigned ah[2][4], al[2][4];
#pragma unroll
            for (int mt = 0; mt < 2; mt++) {
                int r0 = warpM * 32 + mt * 16;
                ah[mt][0] = *(const unsigned*)&xs_h[r0 + g][kb + tg * 2];
                ah[mt][1] = *(const unsigned*)&xs_h[r0 + g + 8][kb + tg * 2];
                ah[mt][2] = *(const unsigned*)&xs_h[r0 + g][kb + tg * 2 + 8];
                ah[mt][3] = *(const unsigned*)&xs_h[r0 + g + 8][kb + tg * 2 + 8];
                al[mt][0] = *(const unsigned*)&xs_l[r0 + g][kb + tg * 2];
                al[mt][1] = *(const unsigned*)&xs_l[r0 + g + 8][kb + tg * 2];
                al[mt][2] = *(const unsigned*)&xs_l[r0 + g][kb + tg * 2 + 8];
                al[mt][3] = *(const unsigned*)&xs_l[r0 + g + 8][kb + tg * 2 + 8];
            }
#pragma unroll
            for (int nt = 0; nt < 8; nt++) {
                int c = warpN * 64 + nt * 8 + g;
                unsigned bh[2], bl[2];
                bh[0] = *(const unsigned*)&ws_h[c][kb + tg * 2];
                bh[1] = *(const unsigned*)&ws_h[c][kb + tg * 2 + 8];
                bl[0] = *(const unsigned*)&ws_l[c][kb + tg * 2];
                bl[1] = *(const unsigned*)&ws_l[c][kb + tg * 2 + 8];
#pragma unroll
                for (int mt = 0; mt < 2; mt++) {
                    mma_f16(acc[mt][nt], ah[mt], bh);
                    mma_f16(acc[mt][nt], al[mt], bh);
                    mma_f16(acc[mt][nt], ah[mt], bl);
                }
            }
        }
        __syncthreads();
    }

    // epilogue: fp32 + fp16 copies
    // C frag: c0,c1 -> (row g,   cols tg*2, tg*2+1); c2,c3 -> row g+8
#pragma unroll
    for (int mt = 0; mt < 2; mt++) {
#pragma unroll
        for (int nt = 0; nt < 8; nt++) {
            int row0 = rowBase + warpM * 32 + mt * 16 + g;
            int col = warpN * 64 + nt * 8 + tg * 2;
            if (row0 < N) {
                *(float2*)&g_h[(size_t)row0 * 128 + col] =
                    make_float2(acc[mt][nt][0], acc[mt][nt][1]);
                *(__half2*)&g_hh[(size_t)row0 * 128 + col] =
                    __floats2half2_rn(acc[mt][nt][0], acc[mt][nt][1]);
            }
            int row1 = row0 + 8;
            if (row1 < N) {
                *(float2*)&g_h[(size_t)row1 * 128 + col] =
                    make_float2(acc[mt][nt][2], acc[mt][nt][3]);
                *(__half2*)&g_hh[(size_t)row1 * 128 + col] =
                    __floats2half2_rn(acc[mt][nt][2], acc[mt][nt][3]);
            }
        }
    }
}

// ============================================================
// K2: fused [node logits | dst histogram]
// ============================================================
__global__ __launch_bounds__(256)
void logits_hist(const float* __restrict__ att_s, const float* __restrict__ att_d,
                 int N, const long long* __restrict__ ei, int E, int nbLogits) {
    if ((int)blockIdx.x < nbLogits) {
        int warp = (blockIdx.x * 256 + threadIdx.x) >> 5;
        int lane = threadIdx.x & 31;
        if (warp >= N) return;
        float4 hv = *(const float4*)&g_h[(size_t)warp * 128 + lane * 4];
        float4 s4 = *(const float4*)&att_s[lane * 4];
        float4 d4 = *(const float4*)&att_d[lane * 4];
        float s = hv.x * s4.x + hv.y * s4.y + hv.z * s4.z + hv.w * s4.w;
        float d = hv.x * d4.x + hv.y * d4.y + hv.z * d4.z + hv.w * d4.w;
#pragma unroll
        for (int o = 16; o > 0; o >>= 1) {
            s += __shfl_xor_sync(0xffffffffu, s, o);
            d += __shfl_xor_sync(0xffffffffu, d, o);
        }
        if (lane == 0) {
            g_as[warp] = s;
            g_ad[warp] = d;
        }
    } else {
        int t = (blockIdx.x - nbLogits) * 256 + threadIdx.x;
        int base = t * 8;
        if (base >= E) return;
        int n = E - base; if (n > 8) n = 8;
        int d[8];
        if (g_is64) {
            if (n == 8 && (E & 1) == 0) {
                const longlong2* p = (const longlong2*)(ei + (size_t)E + base);
#pragma unroll
                for (int j = 0; j < 4; j++) {
                    longlong2 v = p[j];
                    d[2 * j] = (int)v.x; d[2 * j + 1] = (int)v.y;
                }
            } else {
                for (int j = 0; j < n; j++) d[j] = (int)ei[(size_t)E + base + j];
            }
        } else {
            const int* p32 = (const int*)ei;
            if (n == 8 && (E & 3) == 0) {
                const int4* p = (const int4*)(p32 + E + base);
                int4 v0 = p[0], v1 = p[1];
                d[0] = v0.x; d[1] = v0.y; d[2] = v0.z; d[3] = v0.w;
                d[4] = v1.x; d[5] = v1.y; d[6] = v1.z; d[7] = v1.w;
            } else {
                for (int j = 0; j < n; j++) d[j] = p32[E + base + j];
            }
        }
#pragma unroll
        for (int j = 0; j < 8; j++)
            if (j < n) atomicAdd(&g_deg[d[j]], 1);
    }
}

// ============================================================
// K3a: shfl-based block scan (256/block) + block totals
// ============================================================
__global__ void scan_blocks(int N) {
    __shared__ int wt[8];
    int tid = threadIdx.x;
    int lane = tid & 31, wid = tid >> 5;
    int i = blockIdx.x * 256 + tid;
    int v = (i < N) ? g_deg[i] : 0;
    int s = v;
#pragma unroll
    for (int o = 1; o < 32; o <<= 1) {
        int t = __shfl_up_sync(0xffffffffu, s, o);
        if (lane >= o) s += t;
    }
    if (lane == 31) wt[wid] = s;
    __syncthreads();
    if (wid == 0 && lane < 8) {
        int w = wt[lane];
#pragma unroll
        for (int o = 1; o < 8; o <<= 1) {
            int t = __shfl_up_sync(0xffu, w, o);
            if (lane >= o) w += t;
        }
        wt[lane] = w;
    }
    __syncthreads();
    int excl = s - v + (wid > 0 ? wt[wid - 1] : 0);
    if (i < N) g_scan[i] = excl;
    if (tid == 255) g_bt[blockIdx.x] = wt[7];
}

// ============================================================
// K3b: shfl-based scan of block totals, set g_off[N]=E
// ============================================================
__global__ void scan_totals(int nb, int E, int N) {
    __shared__ int wt[8];
    int tid = threadIdx.x;
    int lane = tid & 31, wid = tid >> 5;
    int v = (tid < nb) ? g_bt[tid] : 0;
    int s = v;
#pragma unroll
    for (int o = 1; o < 32; o <<= 1) {
        int t = __shfl_up_sync(0xffffffffu, s, o);
        if (lane >= o) s += t;
    }
    if (lane == 31) wt[wid] = s;
    __syncthreads();
    if (wid == 0 && lane < 8) {
        int w = wt[lane];
#pragma unroll
        for (int o = 1; o < 8; o <<= 1) {
            int t = __shfl_up_sync(0xffu, w, o);
            if (lane >= o) w += t;
        }
        wt[lane] = w;
    }
    __syncthreads();
    g_bt[tid] = s - v + (wid > 0 ? wt[wid - 1] : 0);
    if (tid == 0) g_off[N] = E;
}

// ============================================================
// K3c: add back -> CSR offsets + cursors
// ============================================================
__global__ void scan_addback(int N) {
    int i = blockIdx.x * 256 + threadIdx.x;
    if (i >= N) return;
    int o = g_scan[i] + g_bt[blockIdx.x];
    g_off[i] = o;
    g_cur[i] = o;
}

// ============================================================
// K4: fill CSR slots with src indices (8 edges/thread, vectorized)
// ============================================================
__global__ __launch_bounds__(256)
void fill_kernel(const long long* __restrict__ ei, int E) {
    int t = blockIdx.x * 256 + threadIdx.x;
    int base = t * 8;
    if (base >= E) return;
    int n = E - base; if (n > 8) n = 8;
    int s[8], d[8];
    if (g_is64) {
        if (n == 8 && (E & 1) == 0) {
            const longlong2* ps = (const longlong2*)(ei + base);
            const longlong2* pd = (const longlong2*)(ei + (size_t)E + base);
#pragma unroll
            for (int j = 0; j < 4; j++) {
                longlong2 vs = ps[j], vd = pd[j];
                s[2 * j] = (int)vs.x; s[2 * j + 1] = (int)vs.y;
                d[2 * j] = (int)vd.x; d[2 * j + 1] = (int)vd.y;
            }
        } else {
            for (int j = 0; j < n; j++) {
                s[j] = (int)ei[base + j];
                d[j] = (int)ei[(size_t)E + base + j];
            }
        }
    } else {
        const int* p32 = (const int*)ei;
        if (n == 8 && (E & 3) == 0) {
            const int4* ps = (const int4*)(p32 + base);
            const int4* pd = (const int4*)(p32 + E + base);
            int4 a0 = ps[0], a1 = ps[1], b0 = pd[0], b1 = pd[1];
            s[0] = a0.x; s[1] = a0.y; s[2] = a0.z; s[3] = a0.w;
            s[4] = a1.x; s[5] = a1.y; s[6] = a1.z; s[7] = a1.w;
            d[0] = b0.x; d[1] = b0.y; d[2] = b0.z; d[3] = b0.w;
            d[4] = b1.x; d[5] = b1.y; d[6] = b1.z; d[7] = b1.w;
        } else {
            for (int j = 0; j < n; j++) {
                s[j] = p32[base + j];
                d[j] = p32[E + base + j];
            }
        }
    }
#pragma unroll
    for (int j = 0; j < 8; j++)
        if (j < n) {
            int slot = atomicAdd(&g_cur[d[j]], 1);
            g_eidx[slot] = s[j];
        }
}

// ============================================================
// K5: fused softmax + aggregate (warp per dst, fp16 gathers)
// ============================================================
__global__ __launch_bounds__(256)
void aggregate(float* __restrict__ out, const float* __restrict__ bias, int N) {
    int node = (blockIdx.x * blockDim.x + threadIdx.x) >> 5;
    int lane = threadIdx.x & 31;
    if (node >= N) return;

    float ad = g_ad[node];
    float e0 = g_as[node] + ad;
    e0 = e0 > 0.f ? e0 : SLOPE * e0;
    float pself = expf(e0);

    const __half2* hp0 = (const __half2*)&g_hh[(size_t)node * 128 + lane * 4];
    float2 f0 = __half22float2(hp0[0]);
    float2 f1 = __half22float2(hp0[1]);
    float4 acc;
    acc.x = pself * f0.x;
    acc.y = pself * f0.y;
    acc.z = pself * f1.x;
    acc.w = pself * f1.y;
    float den = pself;

    int beg = g_off[node];
    int end = g_off[node + 1];
    for (int base = beg; base < end; base += 32) {
        int e = base + lane;
        int s = (e < end) ? g_eidx[e] : 0;
        int nv = end - base;
        if (nv > 32) nv = 32;
#pragma unroll 4
        for (int j = 0; j < nv; j++) {
            int sj = __shfl_sync(0xffffffffu, s, j);
            float v = g_as[sj] + ad;
            v = v > 0.f ? v : SLOPE * v;
            float p = expf(v);
            const __half2* hp = (const __half2*)&g_hh[(size_t)sj * 128 + lane * 4];
            float2 a0 = __half22float2(hp[0]);
            float2 a1 = __half22float2(hp[1]);
            den += p;
            acc.x += p * a0.x;
            acc.y += p * a0.y;
            acc.z += p * a1.x;
            acc.w += p * a1.y;
        }
    }

    float inv = 1.f / den;
    float4 b = *(const float4*)&bias[lane * 4];
    float4 o;
    o.x = acc.x * inv + b.x;
    o.y = acc.y * inv + b.y;
    o.z = acc.z * inv + b.z;
    o.w = acc.w * inv + b.w;
    *(float4*)&out[(size_t)node * 128 + lane * 4] = o;
}

// ============================================================
extern "C" void kernel_launch(void* const* d_in, const int* in_sizes, int n_in,
                              void* d_out, int out_size) {
    const float*     x     = (const float*)d_in[0];
    const long long* ei    = (const long long*)d_in[1];
    const float*     W     = (const float*)d_in[2];
    const float*     att_s = (const float*)d_in[3];
    const float*     att_d = (const float*)d_in[4];
    const float*     bias  = (const float*)d_in[5];
    float*           out   = (float*)d_out;

    int N = in_sizes[0] / 128;
    int E = in_sizes[1] / 2;
    int nb = (N + 255) / 256;
    int nbLogits = (N + 7) / 8;
    int nbHist = ((E + 7) / 8 + 255) / 256;

    detect_kernel<<<1, 1024>>>(ei, E, N);
    wprep_kernel<<<64, 256>>>(W);
    gemm_f16x3<<<(N + 127) / 128, 256>>>(x, N);
    logits_hist<<<nbLogits + nbHist, 256>>>(att_s, att_d, N, ei, E, nbLogits);
    scan_blocks<<<nb, 256>>>(N);
    scan_totals<<<1, 256>>>(nb, E, N);
    scan_addback<<<nb, 256>>>(N);
    fill_kernel<<<((E + 7) / 8 + 255) / 256, 256>>>(ei, E);
    aggregate<<<(N * 32 + 255) / 256, 256>>>(out, bias, N);
}